// round 1
// baseline (speedup 1.0000x reference)
#include <cuda_runtime.h>
#include <math.h>

#define TPB 128
#define FSTR 191   // per-thread feature stride in smem floats (191 mod 32 = 31 -> conflict-free)

// ---- shared memory float offsets ----
#define W1P_OFF   0        // conv1 packed [oc][c][12] : 20*21*12 = 5040
#define W2P_OFF   5040     // conv2 packed [oc][oc2][4]: 20*30*4  = 2400
#define FC1P_OFF  7440     // fc1 packed  [j1][32] (cols 0..29, pad 0): 120*32 = 3840
#define FC1OH_OFF 11280    // fc1 one-hot columns [j1][8]: 960
#define FC2T_OFF  12240    // fc2 transposed [j1][84]: 120*84 = 10080
#define FC3W_OFF  22320    // 84
#define B1_OFF    22404    // 20
#define B2_OFF    22424    // 30
#define FB1_OFF   22456    // 120
#define FB2_OFF   22576    // 84
#define FB3_OFF   22660    // 1 (+3 pad)
#define FEAT_OFF  22664
#define SMEM_FLOATS (FEAT_OFF + TPB * FSTR)          // 47112
#define SMEM_BYTES  (SMEM_FLOATS * 4)                // 188448

__global__ void __launch_bounds__(TPB, 1)
disc_kernel(const int* __restrict__ state, const int* __restrict__ des,
            const int* __restrict__ act,
            const int* __restrict__ asp, const int* __restrict__ pm,
            const float* __restrict__ path_feature,
            const float* __restrict__ link_feature,
            const float* __restrict__ c1w, const float* __restrict__ c1b,
            const float* __restrict__ c2w, const float* __restrict__ c2b,
            const float* __restrict__ f1w, const float* __restrict__ f1b,
            const float* __restrict__ f2w, const float* __restrict__ f2b,
            const float* __restrict__ f3w, const float* __restrict__ f3b,
            float* __restrict__ out, int B)
{
    extern __shared__ float sm[];
    const int tid = threadIdx.x;

    // ---------- stage + repack weights into smem (single pass, no races) ----------
    for (int i = tid; i < 5040; i += TPB) {      // conv1: [oc][c][k(0..8)] -> stride 12, pad 0
        int k = i % 12; int oc = i / 252; int c = (i % 252) / 12;
        sm[W1P_OFF + i] = (k < 9) ? c1w[(oc * 21 + c) * 9 + k] : 0.f;
    }
    for (int i = tid; i < 2400; i += TPB) {      // conv2: (30,20,2,2) -> [oc][oc2][4]
        int oc = i / 120; int rem = i % 120; int oc2 = rem / 4; int q = rem % 4;
        sm[W2P_OFF + i] = c2w[(oc2 * 20 + oc) * 4 + q];
    }
    for (int i = tid; i < 3840; i += TPB) {      // fc1 cols 0..29, stride 32, pad 0
        int j = i / 32; int k = i % 32;
        sm[FC1P_OFF + i] = (k < 30) ? f1w[j * 38 + k] : 0.f;
    }
    for (int i = tid; i < 960; i += TPB) {       // fc1 one-hot columns
        int j = i / 8; int aa = i % 8;
        sm[FC1OH_OFF + i] = f1w[j * 38 + 30 + aa];
    }
    for (int i = tid; i < 10080; i += TPB) {     // fc2 transposed [j1][j2]
        int j1 = i / 84; int j2 = i % 84;
        sm[FC2T_OFF + i] = f2w[j2 * 120 + j1];
    }
    for (int i = tid; i < 84; i += TPB) sm[FC3W_OFF + i] = f3w[i];
    if (tid < 20) sm[B1_OFF + tid] = c1b[tid];
    if (tid < 30) sm[B2_OFF + tid] = c2b[tid];
    if (tid < 120) sm[FB1_OFF + tid] = f1b[tid];
    if (tid < 84) sm[FB2_OFF + tid] = f2b[tid];
    if (tid == 0) sm[FB3_OFF] = f3b[0];
    __syncthreads();

    const int b = blockIdx.x * TPB + tid;
    if (b >= B) return;

    const int s = state[b];
    const int dd = des[b];
    const int a = act[b];

    float* F = sm + FEAT_OFF + tid * FSTR;   // private 189-float feature block [c][p]

    // inverse of NEW_INDEX = [7,0,1,6,8,2,5,4,3]
    const int invp[9] = {1, 2, 5, 8, 7, 6, 3, 0, 4};

    // ---------- gather features ----------
#pragma unroll
    for (int r = 0; r < 9; ++r) {
        const int n = asp[s * 9 + r];
        const int p = invp[r];
        const float4* pf = reinterpret_cast<const float4*>(
            path_feature + ((size_t)n * 300 + (size_t)dd) * 12);
        float4 a0 = pf[0], a1 = pf[1], a2 = pf[2];
        F[0 * 9 + p] = a0.x;  F[1 * 9 + p] = a0.y;  F[2 * 9 + p] = a0.z;  F[3 * 9 + p] = a0.w;
        F[4 * 9 + p] = a1.x;  F[5 * 9 + p] = a1.y;  F[6 * 9 + p] = a1.z;  F[7 * 9 + p] = a1.w;
        F[8 * 9 + p] = a2.x;  F[9 * 9 + p] = a2.y;  F[10 * 9 + p] = a2.z; F[11 * 9 + p] = a2.w;
        const float4* lf = reinterpret_cast<const float4*>(link_feature + (size_t)n * 8);
        float4 b0 = lf[0], b1 = lf[1];
        F[12 * 9 + p] = b0.x; F[13 * 9 + p] = b0.y; F[14 * 9 + p] = b0.z; F[15 * 9 + p] = b0.w;
        F[16 * 9 + p] = b1.x; F[17 * 9 + p] = b1.y; F[18 * 9 + p] = b1.z; F[19 * 9 + p] = b1.w;
        F[20 * 9 + p] = (float)pm[s * 9 + r];
    }

    // ---------- conv1 (3x3, pad 1) + lrelu + maxpool(2x2,s1) + conv2 (2x2) fused ----------
    float acc2[30];
#pragma unroll
    for (int j = 0; j < 30; ++j) acc2[j] = sm[B2_OFF + j];

#pragma unroll 1
    for (int ocg = 0; ocg < 4; ++ocg) {          // 4 groups of 5 output channels
        float o[5][9];
#pragma unroll
        for (int u = 0; u < 5; ++u) {
            float bb = sm[B1_OFF + ocg * 5 + u];
#pragma unroll
            for (int k = 0; k < 9; ++k) o[u][k] = bb;
        }
#pragma unroll 1
        for (int c = 0; c < 21; ++c) {
            float f[9];
#pragma unroll
            for (int k = 0; k < 9; ++k) f[k] = F[c * 9 + k];
#pragma unroll
            for (int u = 0; u < 5; ++u) {
                const float* wp = sm + W1P_OFF + ((ocg * 5 + u) * 21 + c) * 12;
                float4 wa = *reinterpret_cast<const float4*>(wp);
                float4 wb = *reinterpret_cast<const float4*>(wp + 4);
                float w8 = wp[8];
                float wreg[9] = {wa.x, wa.y, wa.z, wa.w, wb.x, wb.y, wb.z, wb.w, w8};
#pragma unroll
                for (int ky = 0; ky < 3; ++ky)
#pragma unroll
                for (int kx = 0; kx < 3; ++kx) {
                    float wv = wreg[ky * 3 + kx];
#pragma unroll
                    for (int y = 0; y < 3; ++y) {
                        int iy = y + ky - 1;
                        if (iy < 0 || iy > 2) continue;
#pragma unroll
                        for (int xx = 0; xx < 3; ++xx) {
                            int ix = xx + kx - 1;
                            if (ix < 0 || ix > 2) continue;
                            o[u][y * 3 + xx] += wv * f[iy * 3 + ix];
                        }
                    }
                }
            }
        }
        // lrelu + pool + conv2 accumulate for these 5 channels
#pragma unroll
        for (int u = 0; u < 5; ++u) {
            float q[9];
#pragma unroll
            for (int k = 0; k < 9; ++k) { float v = o[u][k]; q[k] = fmaxf(v, 0.2f * v); }
            float p00 = fmaxf(fmaxf(q[0], q[1]), fmaxf(q[3], q[4]));
            float p01 = fmaxf(fmaxf(q[1], q[2]), fmaxf(q[4], q[5]));
            float p10 = fmaxf(fmaxf(q[3], q[4]), fmaxf(q[6], q[7]));
            float p11 = fmaxf(fmaxf(q[4], q[5]), fmaxf(q[7], q[8]));
            const float4* wq = reinterpret_cast<const float4*>(sm + W2P_OFF + (ocg * 5 + u) * 120);
#pragma unroll
            for (int oc2 = 0; oc2 < 30; ++oc2) {
                float4 w = wq[oc2];
                acc2[oc2] += p00 * w.x + p01 * w.y + p10 * w.z + p11 * w.w;
            }
        }
    }

    // ---------- fc1 + fc2 fused (one-hot folded into a column lookup) ----------
    float x[32];
#pragma unroll
    for (int j = 0; j < 30; ++j) { float v = acc2[j]; x[j] = fmaxf(v, 0.2f * v); }
    x[30] = 0.f; x[31] = 0.f;

    float h2[84];
#pragma unroll
    for (int j = 0; j < 84; ++j) h2[j] = sm[FB2_OFF + j];

#pragma unroll 1
    for (int j1 = 0; j1 < 120; ++j1) {
        const float4* wp = reinterpret_cast<const float4*>(sm + FC1P_OFF + j1 * 32);
        float t0 = 0.f, t1 = 0.f, t2 = 0.f, t3 = 0.f;
#pragma unroll
        for (int qq = 0; qq < 8; ++qq) {
            float4 w = wp[qq];
            t0 += w.x * x[qq * 4 + 0];
            t1 += w.y * x[qq * 4 + 1];
            t2 += w.z * x[qq * 4 + 2];
            t3 += w.w * x[qq * 4 + 3];
        }
        float t = sm[FB1_OFF + j1] + sm[FC1OH_OFF + j1 * 8 + a] + ((t0 + t1) + (t2 + t3));
        t = fmaxf(t, 0.2f * t);
        const float4* w2 = reinterpret_cast<const float4*>(sm + FC2T_OFF + j1 * 84);
#pragma unroll
        for (int g = 0; g < 21; ++g) {
            float4 w = w2[g];
            h2[g * 4 + 0] += t * w.x;
            h2[g * 4 + 1] += t * w.y;
            h2[g * 4 + 2] += t * w.z;
            h2[g * 4 + 3] += t * w.w;
        }
    }

    // ---------- fc3 + sigmoid ----------
    float z = sm[FB3_OFF];
#pragma unroll
    for (int j = 0; j < 84; ++j) {
        float v = h2[j];
        v = fmaxf(v, 0.2f * v);
        z += v * sm[FC3W_OFF + j];
    }
    out[b] = 1.f / (1.f + expf(-z));
}

extern "C" void kernel_launch(void* const* d_in, const int* in_sizes, int n_in,
                              void* d_out, int out_size)
{
    const int*   state = (const int*)d_in[0];
    const int*   des   = (const int*)d_in[1];
    const int*   act   = (const int*)d_in[2];
    const int*   asp   = (const int*)d_in[3];
    const int*   pm    = (const int*)d_in[4];
    const float* pf    = (const float*)d_in[5];
    const float* lf    = (const float*)d_in[6];
    const float* c1w   = (const float*)d_in[7];
    const float* c1b   = (const float*)d_in[8];
    const float* c2w   = (const float*)d_in[9];
    const float* c2b   = (const float*)d_in[10];
    const float* f1w   = (const float*)d_in[11];
    const float* f1b   = (const float*)d_in[12];
    const float* f2w   = (const float*)d_in[13];
    const float* f2b   = (const float*)d_in[14];
    const float* f3w   = (const float*)d_in[15];
    const float* f3b   = (const float*)d_in[16];

    const int B = in_sizes[0];
    float* out = (float*)d_out;

    cudaFuncSetAttribute(disc_kernel, cudaFuncAttributeMaxDynamicSharedMemorySize, SMEM_BYTES);

    const int grid = (B + TPB - 1) / TPB;
    disc_kernel<<<grid, TPB, SMEM_BYTES>>>(state, des, act, asp, pm, pf, lf,
                                           c1w, c1b, c2w, c2b,
                                           f1w, f1b, f2w, f2b, f3w, f3b,
                                           out, B);
}

// round 2
// speedup vs baseline: 1.1002x; 1.1002x over previous
#include <cuda_runtime.h>
#include <math.h>

typedef unsigned long long ull;

#define TPB 128

// ---- shared memory float offsets ----
#define W1_OFF    0        // conv1 repacked [c][tap][oc] : 21*9*20 = 3780
#define W2_OFF    3780     // conv2 repacked [oc][q][oc2 pad32] : 20*4*32 = 2560
#define FC1P_OFF  6340     // fc1 [j1][32] (cols 0..29, pad 0) : 3840
#define FC1OH_OFF 10180    // fc1 one-hot cols [j1][8] : 960
#define FC2T_OFF  11140    // fc2 transposed [j1][84] : 10080
#define FC3_OFF   21220    // 84
#define B1_OFF    21304    // 20
#define B2P_OFF   21324    // 32 (30 + zero pad)
#define FB1_OFF   21356    // 120
#define FB2_OFF   21476    // 84
#define FB3_OFF   21560    // 1 (+3 pad)
#define FEAT_OFF  21564    // per-thread 21-float buffer
#define SMEM_FLOATS (FEAT_OFF + TPB * 21)     // 24252
#define SMEM_BYTES  (SMEM_FLOATS * 4)         // 97008 -> 2 blocks/SM

__device__ __forceinline__ ull ffma2(ull a, ull b, ull c) {
    ull d; asm("fma.rn.f32x2 %0,%1,%2,%3;" : "=l"(d) : "l"(a), "l"(b), "l"(c)); return d;
}
__device__ __forceinline__ ull pack2(float lo, float hi) {
    ull d; asm("mov.b64 %0,{%1,%2};" : "=l"(d) : "f"(lo), "f"(hi)); return d;
}
__device__ __forceinline__ void unpack2(ull v, float& lo, float& hi) {
    asm("mov.b64 {%0,%1},%2;" : "=f"(lo), "=f"(hi) : "l"(v));
}

// conv1 contribution of the neighbor sitting at grid position (PY,PX):
// o[oc][q] += f[c] * w1[oc][c][tap],  tap = (1-dy)*3+(1-dx), q = (PY+dy)*3+(PX+dx)
template<int PY, int PX>
__device__ __forceinline__ void nconv(const float* __restrict__ sm,
                                      const float* __restrict__ Fb,
                                      ull (&o2)[10][9]) {
#pragma unroll 3
    for (int c = 0; c < 21; ++c) {
        float fv = Fb[c];
        ull fc2 = pack2(fv, fv);
#pragma unroll
        for (int dy = -1; dy <= 1; ++dy) {
            if (PY + dy < 0 || PY + dy > 2) continue;
#pragma unroll
            for (int dx = -1; dx <= 1; ++dx) {
                if (PX + dx < 0 || PX + dx > 2) continue;
                const int tap = (1 - dy) * 3 + (1 - dx);
                const int q = (PY + dy) * 3 + (PX + dx);
                const ulonglong2* wp = reinterpret_cast<const ulonglong2*>(
                    sm + W1_OFF + (c * 9 + tap) * 20);
                ulonglong2 w0 = wp[0], w1 = wp[1], w2 = wp[2], w3 = wp[3], w4 = wp[4];
                o2[0][q] = ffma2(w0.x, fc2, o2[0][q]);
                o2[1][q] = ffma2(w0.y, fc2, o2[1][q]);
                o2[2][q] = ffma2(w1.x, fc2, o2[2][q]);
                o2[3][q] = ffma2(w1.y, fc2, o2[3][q]);
                o2[4][q] = ffma2(w2.x, fc2, o2[4][q]);
                o2[5][q] = ffma2(w2.y, fc2, o2[5][q]);
                o2[6][q] = ffma2(w3.x, fc2, o2[6][q]);
                o2[7][q] = ffma2(w3.y, fc2, o2[7][q]);
                o2[8][q] = ffma2(w4.x, fc2, o2[8][q]);
                o2[9][q] = ffma2(w4.y, fc2, o2[9][q]);
            }
        }
    }
}

__global__ void __launch_bounds__(TPB, 2)
disc_kernel(const int* __restrict__ state, const int* __restrict__ des,
            const int* __restrict__ act,
            const int* __restrict__ asp, const int* __restrict__ pm,
            const float* __restrict__ path_feature,
            const float* __restrict__ link_feature,
            const float* __restrict__ c1w, const float* __restrict__ c1b,
            const float* __restrict__ c2w, const float* __restrict__ c2b,
            const float* __restrict__ f1w, const float* __restrict__ f1b,
            const float* __restrict__ f2w, const float* __restrict__ f2b,
            const float* __restrict__ f3w, const float* __restrict__ f3b,
            float* __restrict__ out, int B)
{
    extern __shared__ float sm[];
    const int tid = threadIdx.x;

    // ---------- stage + repack weights ----------
    for (int i = tid; i < 3780; i += TPB) {            // W1 [c][tap][oc]
        int c = i / 180; int rem = i % 180; int tap = rem / 20; int oc = rem % 20;
        sm[W1_OFF + i] = c1w[(oc * 21 + c) * 9 + tap];
    }
    for (int i = tid; i < 2560; i += TPB) {            // W2 [oc][q][oc2 pad 32]
        int oc = i / 128; int rem = i % 128; int q = rem / 32; int oc2 = rem % 32;
        sm[W2_OFF + i] = (oc2 < 30) ? c2w[(oc2 * 20 + oc) * 4 + q] : 0.f;
    }
    for (int i = tid; i < 3840; i += TPB) {            // FC1 [j1][32]
        int j = i / 32; int k = i % 32;
        sm[FC1P_OFF + i] = (k < 30) ? f1w[j * 38 + k] : 0.f;
    }
    for (int i = tid; i < 960; i += TPB) {             // FC1 one-hot cols
        int j = i / 8; int aa = i % 8;
        sm[FC1OH_OFF + i] = f1w[j * 38 + 30 + aa];
    }
    for (int i = tid; i < 10080; i += TPB) {           // FC2 transposed [j1][84]
        int j1 = i / 84; int j2 = i % 84;
        sm[FC2T_OFF + i] = f2w[j2 * 120 + j1];
    }
    for (int i = tid; i < 84; i += TPB) sm[FC3_OFF + i] = f3w[i];
    if (tid < 20) sm[B1_OFF + tid] = c1b[tid];
    if (tid < 32) sm[B2P_OFF + tid] = (tid < 30) ? c2b[tid] : 0.f;
    if (tid < 120) sm[FB1_OFF + tid] = f1b[tid];
    if (tid < 84) sm[FB2_OFF + tid] = f2b[tid];
    if (tid == 0) sm[FB3_OFF] = f3b[0];
    __syncthreads();

    const int b = blockIdx.x * TPB + tid;
    if (b >= B) return;

    const int s = state[b];
    const int dd = des[b];
    const int a = act[b];

    // neighbor indices / masks for all 9 rows (contiguous in asp/pm)
    int nn[9], mm[9];
#pragma unroll
    for (int r = 0; r < 9; ++r) {
        nn[r] = asp[s * 9 + r];
        mm[r] = pm[s * 9 + r];
    }

    float* Fb = sm + FEAT_OFF + tid * 21;   // private 21-float scratch (stride 21, conflict-free)

    // conv1 accumulators: 20 oc as 10 fp32x2 pairs x 9 positions, init = bias
    ull o2[10][9];
#pragma unroll
    for (int u = 0; u < 10; ++u) {
        ull bb = pack2(sm[B1_OFF + 2 * u], sm[B1_OFF + 2 * u + 1]);
#pragma unroll
        for (int q = 0; q < 9; ++q) o2[u][q] = bb;
    }

    float4 v0, v1, v2, v3, v4;
#define LOADN(r) { \
        const float* pp = path_feature + ((size_t)nn[r] * 300 + (size_t)dd) * 12; \
        const float4* pf4 = reinterpret_cast<const float4*>(pp); \
        v0 = pf4[0]; v1 = pf4[1]; v2 = pf4[2]; \
        const float4* lf4 = reinterpret_cast<const float4*>(link_feature + (size_t)nn[r] * 8); \
        v3 = lf4[0]; v4 = lf4[1]; }
#define PUSHF(r) { \
        Fb[0] = v0.x;  Fb[1] = v0.y;  Fb[2] = v0.z;  Fb[3] = v0.w; \
        Fb[4] = v1.x;  Fb[5] = v1.y;  Fb[6] = v1.z;  Fb[7] = v1.w; \
        Fb[8] = v2.x;  Fb[9] = v2.y;  Fb[10] = v2.z; Fb[11] = v2.w; \
        Fb[12] = v3.x; Fb[13] = v3.y; Fb[14] = v3.z; Fb[15] = v3.w; \
        Fb[16] = v4.x; Fb[17] = v4.y; Fb[18] = v4.z; Fb[19] = v4.w; \
        Fb[20] = (float)mm[r]; }

    // invp = {1,2,5,8,7,6,3,0,4}: neighbor r sits at grid position invp[r]
    LOADN(0);
    PUSHF(0); LOADN(1); nconv<0,1>(sm, Fb, o2);   // p=1
    PUSHF(1); LOADN(2); nconv<0,2>(sm, Fb, o2);   // p=2
    PUSHF(2); LOADN(3); nconv<1,2>(sm, Fb, o2);   // p=5
    PUSHF(3); LOADN(4); nconv<2,2>(sm, Fb, o2);   // p=8
    PUSHF(4); LOADN(5); nconv<2,1>(sm, Fb, o2);   // p=7
    PUSHF(5); LOADN(6); nconv<2,0>(sm, Fb, o2);   // p=6
    PUSHF(6); LOADN(7); nconv<1,0>(sm, Fb, o2);   // p=3
    PUSHF(7); LOADN(8); nconv<0,0>(sm, Fb, o2);   // p=0
    PUSHF(8);           nconv<1,1>(sm, Fb, o2);   // p=4
#undef LOADN
#undef PUSHF

    // ---------- lrelu + maxpool(2x2,s1) + conv2 (2x2 VALID) ----------
    ull aa[16];
#pragma unroll
    for (int j = 0; j < 16; ++j)
        aa[j] = pack2(sm[B2P_OFF + 2 * j], sm[B2P_OFF + 2 * j + 1]);

#pragma unroll
    for (int u = 0; u < 10; ++u) {
        float lo[9], hi[9];
#pragma unroll
        for (int q = 0; q < 9; ++q) unpack2(o2[u][q], lo[q], hi[q]);
#pragma unroll
        for (int half = 0; half < 2; ++half) {
            const float* vv = half ? hi : lo;
            const int oc = 2 * u + half;
            float qv[9];
#pragma unroll
            for (int k = 0; k < 9; ++k) { float v = vv[k]; qv[k] = fmaxf(v, 0.2f * v); }
            float pl[4];
            pl[0] = fmaxf(fmaxf(qv[0], qv[1]), fmaxf(qv[3], qv[4]));
            pl[1] = fmaxf(fmaxf(qv[1], qv[2]), fmaxf(qv[4], qv[5]));
            pl[2] = fmaxf(fmaxf(qv[3], qv[4]), fmaxf(qv[6], qv[7]));
            pl[3] = fmaxf(fmaxf(qv[4], qv[5]), fmaxf(qv[7], qv[8]));
#pragma unroll
            for (int q = 0; q < 4; ++q) {
                ull pq = pack2(pl[q], pl[q]);
                const ulonglong2* wp = reinterpret_cast<const ulonglong2*>(
                    sm + W2_OFF + (oc * 4 + q) * 32);
#pragma unroll
                for (int g = 0; g < 8; ++g) {
                    ulonglong2 w = wp[g];
                    aa[2 * g]     = ffma2(w.x, pq, aa[2 * g]);
                    aa[2 * g + 1] = ffma2(w.y, pq, aa[2 * g + 1]);
                }
            }
        }
    }

    // ---------- fc1 + fc2 fused ----------
    ull x2[16];
#pragma unroll
    for (int j = 0; j < 15; ++j) {
        float lo, hi; unpack2(aa[j], lo, hi);
        x2[j] = pack2(fmaxf(lo, 0.2f * lo), fmaxf(hi, 0.2f * hi));
    }
    x2[15] = 0ull;

    ull hh[42];
#pragma unroll
    for (int j = 0; j < 42; ++j)
        hh[j] = pack2(sm[FB2_OFF + 2 * j], sm[FB2_OFF + 2 * j + 1]);

#pragma unroll 2
    for (int j1 = 0; j1 < 120; ++j1) {
        const ulonglong2* wp = reinterpret_cast<const ulonglong2*>(sm + FC1P_OFF + j1 * 32);
        ull t0 = 0ull, t1 = 0ull, t2 = 0ull, t3 = 0ull;
#pragma unroll
        for (int g = 0; g < 4; ++g) {
            ulonglong2 wA = wp[2 * g], wB = wp[2 * g + 1];
            t0 = ffma2(wA.x, x2[4 * g],     t0);
            t1 = ffma2(wA.y, x2[4 * g + 1], t1);
            t2 = ffma2(wB.x, x2[4 * g + 2], t2);
            t3 = ffma2(wB.y, x2[4 * g + 3], t3);
        }
        float s0, s1, s2, s3, s4, s5, s6, s7;
        unpack2(t0, s0, s1); unpack2(t1, s2, s3); unpack2(t2, s4, s5); unpack2(t3, s6, s7);
        float t = sm[FB1_OFF + j1] + sm[FC1OH_OFF + j1 * 8 + a]
                + (((s0 + s1) + (s2 + s3)) + ((s4 + s5) + (s6 + s7)));
        t = fmaxf(t, 0.2f * t);
        ull tt = pack2(t, t);
        const ulonglong2* w2p = reinterpret_cast<const ulonglong2*>(sm + FC2T_OFF + j1 * 84);
#pragma unroll
        for (int g = 0; g < 21; ++g) {
            ulonglong2 w = w2p[g];
            hh[2 * g]     = ffma2(w.x, tt, hh[2 * g]);
            hh[2 * g + 1] = ffma2(w.y, tt, hh[2 * g + 1]);
        }
    }

    // ---------- fc3 + sigmoid ----------
    float z0 = 0.f, z1 = 0.f, z2 = 0.f, z3 = 0.f;
#pragma unroll
    for (int g = 0; g < 42; ++g) {
        float lo, hi; unpack2(hh[g], lo, hi);
        lo = fmaxf(lo, 0.2f * lo); hi = fmaxf(hi, 0.2f * hi);
        if (g & 1) { z2 += lo * sm[FC3_OFF + 2 * g]; z3 += hi * sm[FC3_OFF + 2 * g + 1]; }
        else       { z0 += lo * sm[FC3_OFF + 2 * g]; z1 += hi * sm[FC3_OFF + 2 * g + 1]; }
    }
    float z = sm[FB3_OFF] + ((z0 + z1) + (z2 + z3));
    out[b] = 1.f / (1.f + expf(-z));
}

extern "C" void kernel_launch(void* const* d_in, const int* in_sizes, int n_in,
                              void* d_out, int out_size)
{
    const int*   state = (const int*)d_in[0];
    const int*   des   = (const int*)d_in[1];
    const int*   act   = (const int*)d_in[2];
    const int*   asp   = (const int*)d_in[3];
    const int*   pm    = (const int*)d_in[4];
    const float* pf    = (const float*)d_in[5];
    const float* lf    = (const float*)d_in[6];
    const float* c1w   = (const float*)d_in[7];
    const float* c1b   = (const float*)d_in[8];
    const float* c2w   = (const float*)d_in[9];
    const float* c2b   = (const float*)d_in[10];
    const float* f1w   = (const float*)d_in[11];
    const float* f1b   = (const float*)d_in[12];
    const float* f2w   = (const float*)d_in[13];
    const float* f2b   = (const float*)d_in[14];
    const float* f3w   = (const float*)d_in[15];
    const float* f3b   = (const float*)d_in[16];

    const int B = in_sizes[0];
    float* out = (float*)d_out;

    cudaFuncSetAttribute(disc_kernel, cudaFuncAttributeMaxDynamicSharedMemorySize, SMEM_BYTES);

    const int grid = (B + TPB - 1) / TPB;
    disc_kernel<<<grid, TPB, SMEM_BYTES>>>(state, des, act, asp, pm, pf, lf,
                                           c1w, c1b, c2w, c2b,
                                           f1w, f1b, f2w, f2b, f3w, f3b,
                                           out, B);
}